// round 16
// baseline (speedup 1.0000x reference)
#include <cuda_runtime.h>
#include <cuda_fp16.h>
#include <cstdint>

// Problem dims (fixed by reference setup_inputs)
#define MM   8192      // B*S
#define NN   4096      // D_OUT
#define KK   4096      // D_IN
#define RR   16
#define LORA_SCALING 2.0f

// ---------------------------------------------------------------------------
// Device scratch (static __device__ arrays — no runtime allocation)
// ---------------------------------------------------------------------------
__device__ __half g_xh[(size_t)MM * KK];   // 64 MB: x rounded to fp16
__device__ __half g_wh[(size_t)NN * KK];   // 32 MB: fused dequant+LoRA weight, fp16
// readiness flags: [0,32) weff n-groups (128 out-rows), [32,96) conv m-groups
__device__ int g_flags[96];

// ---------------------------------------------------------------------------
// Helpers (base PTX only — sm_103 target has no 'a'-feature instructions)
// ---------------------------------------------------------------------------
__device__ __forceinline__ uint32_t smem_u32(const void* p) {
    uint32_t a;
    asm("{ .reg .u64 t; cvta.to.shared.u64 t, %1; cvt.u32.u64 %0, t; }"
        : "=r"(a) : "l"(p));
    return a;
}

#define CP_ASYNC16(dst_u32, src_ptr) \
    asm volatile("cp.async.cg.shared.global [%0], [%1], 16;\n" :: "r"(dst_u32), "l"(src_ptr))
#define CP_COMMIT()   asm volatile("cp.async.commit_group;\n" ::)
#define CP_WAIT(n)    asm volatile("cp.async.wait_group %0;\n" :: "n"(n))

#define LDMATRIX_X4(r0, r1, r2, r3, addr)                                     \
    asm volatile("ldmatrix.sync.aligned.m8n8.x4.shared.b16 {%0,%1,%2,%3}, [%4];" \
        : "=r"(r0), "=r"(r1), "=r"(r2), "=r"(r3) : "r"(addr))

#define MMA16816(d, a, b)                                                      \
    asm volatile("mma.sync.aligned.m16n8k16.row.col.f32.f16.f16.f32 "          \
        "{%0,%1,%2,%3}, {%4,%5,%6,%7}, {%8,%9}, {%0,%1,%2,%3};\n"              \
        : "+f"((d)[0]), "+f"((d)[1]), "+f"((d)[2]), "+f"((d)[3])               \
        : "r"((a)[0]), "r"((a)[1]), "r"((a)[2]), "r"((a)[3]),                  \
          "r"((b)[0]), "r"((b)[1]))

// ---------------------------------------------------------------------------
// Mega-kernel block layout
// ---------------------------------------------------------------------------
constexpr int WEFF_BO = 64, WEFF_BI = 256;
constexpr int P_W = (NN / WEFF_BO) * (KK / WEFF_BI);           // 1024 weff blocks
constexpr int P_C = (int)((size_t)MM * KK / 16384);            // 2048 conv blocks (4 rows each)
constexpr int PREP_BLOCKS = P_W + P_C;                         // 3072
// GEMM geometry (byte-identical to the 671.7us R12 configuration)
constexpr int BM = 128, BN = 128, BK = 64;
constexpr int NSTAGES = 3;
constexpr int A_ST = BM * 128;                 // 16 KB per stage
constexpr int STG = 2 * A_ST;                  // 32 KB per stage (A + B)
constexpr int GEMM_SMEM = NSTAGES * STG + 128;
constexpr int KT = KK / BK;                    // 64
constexpr int GEMM_BLOCKS = (NN / BN) * (MM / BM);             // 2048
constexpr int TOTAL_BLOCKS = PREP_BLOCKS + GEMM_BLOCKS;        // 5120

__global__ void __launch_bounds__(256, 2)
mega_kernel(const float4* __restrict__ x,
            const int* __restrict__ wq,
            const float* __restrict__ scale,
            const float* __restrict__ zero,
            const float* __restrict__ lA,
            const float* __restrict__ lB,
            const float* __restrict__ bias,
            float* __restrict__ C) {
    extern __shared__ char dsm[];
    const int tid = threadIdx.x;
    const unsigned bid = blockIdx.x;

    if (bid < (unsigned)P_W) {
        // ================= W_eff build =================
        // W_eff = (wq - zero)*scale + 2 * B @ A  -> fp16   (smem aliased on dsm)
        float (*sA)[WEFF_BI] = (float (*)[WEFF_BI])dsm;              // 16 KB
        float (*sB)[RR]      = (float (*)[RR])(dsm + RR * WEFF_BI * 4); // 4 KB
        float* sS = (float*)(dsm + RR * WEFF_BI * 4 + WEFF_BO * RR * 4);
        float* sZ = sS + WEFF_BO;

        const int b  = bid;
        const int i0 = (b % (KK / WEFF_BI)) * WEFF_BI;
        const int o0 = (b / (KK / WEFF_BI)) * WEFF_BO;

        for (int idx = tid; idx < RR * WEFF_BI; idx += 256) {
            int r = idx / WEFF_BI, i = idx % WEFF_BI;
            sA[r][i] = lA[(size_t)r * KK + i0 + i];
        }
        for (int idx = tid; idx < WEFF_BO * RR; idx += 256) {
            int o = idx / RR, r = idx % RR;
            sB[o][r] = lB[(size_t)(o0 + o) * RR + r];
        }
        if (tid < WEFF_BO) { sS[tid] = scale[o0 + tid]; sZ[tid] = zero[o0 + tid]; }
        __syncthreads();

        constexpr int CH = WEFF_BI / 4;                  // 64 int4 chunks per row
        for (int idx = tid; idx < WEFF_BO * CH; idx += 256) {
            const int o  = idx / CH;
            const int i4 = (idx % CH) * 4;
            const int4 wv = *reinterpret_cast<const int4*>(
                wq + (size_t)(o0 + o) * KK + i0 + i4);
            const float z = sZ[o], s = sS[o];
            float r0 = ((float)wv.x - z) * s;
            float r1 = ((float)wv.y - z) * s;
            float r2 = ((float)wv.z - z) * s;
            float r3 = ((float)wv.w - z) * s;
            float a0 = 0.f, a1 = 0.f, a2 = 0.f, a3 = 0.f;
            #pragma unroll
            for (int r = 0; r < RR; r++) {
                const float br = sB[o][r];
                const float4 av = *reinterpret_cast<const float4*>(&sA[r][i4]);
                a0 += br * av.x; a1 += br * av.y;
                a2 += br * av.z; a3 += br * av.w;
            }
            __half2 h01 = __floats2half2_rn(r0 + LORA_SCALING * a0,
                                            r1 + LORA_SCALING * a1);
            __half2 h23 = __floats2half2_rn(r2 + LORA_SCALING * a2,
                                            r3 + LORA_SCALING * a3);
            uint2 st;
            st.x = *reinterpret_cast<unsigned*>(&h01);
            st.y = *reinterpret_cast<unsigned*>(&h23);
            *reinterpret_cast<uint2*>(g_wh + (size_t)(o0 + o) * KK + i0 + i4) = st;
        }
        // publish: n-group = b >> 5 (32 weff blocks per 128 output rows)
        __threadfence();
        __syncthreads();
        if (tid == 0) atomicAdd(&g_flags[b >> 5], 1);
        return;
    }

    if (bid < (unsigned)PREP_BLOCKS) {
        // ================= x -> fp16 (4 rows per block) =================
        const int cb = bid - P_W;
        size_t base = (size_t)cb * 2048 + tid;   // in float4-pairs (8 floats)
        #pragma unroll
        for (int it = 0; it < 8; it++) {
            size_t i = base + (size_t)it * 256;
            float4 a = x[2 * i], b = x[2 * i + 1];
            __half2 h0 = __floats2half2_rn(a.x, a.y);
            __half2 h1 = __floats2half2_rn(a.z, a.w);
            __half2 h2 = __floats2half2_rn(b.x, b.y);
            __half2 h3 = __floats2half2_rn(b.z, b.w);
            uint4 o;
            o.x = *reinterpret_cast<unsigned*>(&h0);
            o.y = *reinterpret_cast<unsigned*>(&h1);
            o.z = *reinterpret_cast<unsigned*>(&h2);
            o.w = *reinterpret_cast<unsigned*>(&h3);
            ((uint4*)g_xh)[i] = o;
        }
        // publish: m-group = cb >> 5 (32 conv blocks per 128 input rows)
        __threadfence();
        __syncthreads();
        if (tid == 0) atomicAdd(&g_flags[32 + (cb >> 5)], 1);
        return;
    }

    // ================= GEMM (R12 mainloop, verbatim) =================
    const int g  = bid - PREP_BLOCKS;
    const int bx = g & 31;             // n-tile 0..31
    const int by = g >> 5;             // m-tile 0..63
    const int m0 = by * BM;
    const int n0 = bx * BN;

    // ---- wait for producers of this tile's rows ----
    if (tid == 0) {
        volatile int* fw = &g_flags[bx];        // weff n-group == bx
        volatile int* fx = &g_flags[32 + by];   // conv m-group == by
        while (*fw < 32) { __nanosleep(200); }
        while (*fx < 32) { __nanosleep(200); }
        __threadfence();
    }
    __syncthreads();

    const uint32_t tile = (smem_u32(dsm) + 127u) & ~127u;   // 128B-align
    const int warp = tid >> 5;
    const int lane = tid & 31;

    // ---- cp.async mapping: 2048 16B chunks / 256 threads = 8 each (4 A, 4 B)
    const __half* gA = g_xh + (size_t)m0 * KK;
    const __half* gB = g_wh + (size_t)n0 * KK;
    uint32_t soff[8];
    uint32_t doff[8];
    #pragma unroll
    for (int j = 0; j < 8; j++) {
        int c = tid + (j & 3) * 256;
        int row = c >> 3, c16 = c & 7;
        soff[j] = (uint32_t)(row * KK + c16 * 8);
        doff[j] = (uint32_t)((j < 4 ? 0 : A_ST) + row * 128 + ((c16 ^ (row & 7)) << 4));
    }

    #define ISSUE_STAGE(kt_, s_) do {                                          \
        uint32_t base_ = tile + (s_) * STG;                                    \
        _Pragma("unroll")                                                      \
        for (int j = 0; j < 4; j++)                                            \
            CP_ASYNC16(base_ + doff[j], gA + soff[j] + (kt_) * BK);            \
        _Pragma("unroll")                                                      \
        for (int j = 4; j < 8; j++)                                            \
            CP_ASYNC16(base_ + doff[j], gB + soff[j] + (kt_) * BK);            \
        CP_COMMIT();                                                           \
    } while (0)

    const int wm = (warp & 3) * 32;
    const int wn = (warp >> 2) * 64;
    const int gid = lane >> 2;
    const int tig = lane & 3;
    const int l7  = lane & 7;

    uint32_t a_row[2];
    #pragma unroll
    for (int mi = 0; mi < 2; mi++)
        a_row[mi] = (uint32_t)((wm + mi * 16 + (lane & 15)) * 128);
    const uint32_t a_cx = (uint32_t)(lane >> 4);
    uint32_t b_row[4];
    #pragma unroll
    for (int ng = 0; ng < 4; ng++)
        b_row[ng] = (uint32_t)((wn + ng * 16 + l7 + ((lane >> 4) << 3)) * 128);
    const uint32_t b_cx = (uint32_t)((lane >> 3) & 1);

    float acc[2][8][4];
    #pragma unroll
    for (int a = 0; a < 2; a++)
        #pragma unroll
        for (int b = 0; b < 8; b++)
            #pragma unroll
            for (int c = 0; c < 4; c++) acc[a][b][c] = 0.f;

    ISSUE_STAGE(0, 0);
    ISSUE_STAGE(1, 1);

    int s = 0;
    for (int kt = 0; kt < KT; kt++) {
        CP_WAIT(1);
        __syncthreads();
        if (kt + 2 < KT) {
            int sn = s + 2; if (sn >= NSTAGES) sn -= NSTAGES;
            ISSUE_STAGE(kt + 2, sn);
        }

        const uint32_t sA = tile + s * STG;
        const uint32_t sB = sA + A_ST;

        #pragma unroll
        for (int ks = 0; ks < 4; ks++) {
            const uint32_t kc = (uint32_t)(ks * 2);
            uint32_t af[2][4], bf[8][2];
            #pragma unroll
            for (int mi = 0; mi < 2; mi++) {
                uint32_t addr = sA + a_row[mi] + (((kc + a_cx) ^ l7) << 4);
                LDMATRIX_X4(af[mi][0], af[mi][1], af[mi][2], af[mi][3], addr);
            }
            #pragma unroll
            for (int ng = 0; ng < 4; ng++) {
                uint32_t addr = sB + b_row[ng] + (((kc + b_cx) ^ l7) << 4);
                LDMATRIX_X4(bf[2 * ng][0], bf[2 * ng][1],
                            bf[2 * ng + 1][0], bf[2 * ng + 1][1], addr);
            }
            #pragma unroll
            for (int mi = 0; mi < 2; mi++)
                #pragma unroll
                for (int ni = 0; ni < 8; ni++)
                    MMA16816(acc[mi][ni], af[mi], bf[ni]);
        }
        if (++s == NSTAGES) s = 0;
    }

    #pragma unroll
    for (int mi = 0; mi < 2; mi++) {
        const int row0 = m0 + wm + mi * 16 + gid;
        #pragma unroll
        for (int ni = 0; ni < 8; ni++) {
            const int col = n0 + wn + ni * 8 + tig * 2;
            const float b0 = __ldg(bias + col);
            const float b1 = __ldg(bias + col + 1);
            float2 v0 = make_float2(acc[mi][ni][0] + b0, acc[mi][ni][1] + b1);
            float2 v1 = make_float2(acc[mi][ni][2] + b0, acc[mi][ni][3] + b1);
            *(float2*)(C + (size_t)row0 * NN + col)       = v0;
            *(float2*)(C + (size_t)(row0 + 8) * NN + col) = v1;
        }
    }
    #undef ISSUE_STAGE
}

// ---------------------------------------------------------------------------
// Launch
// ---------------------------------------------------------------------------
extern "C" void kernel_launch(void* const* d_in, const int* in_sizes, int n_in,
                              void* d_out, int out_size) {
    const float* x     = (const float*)d_in[0];
    const int*   wq    = (const int*)  d_in[1];
    const float* scale = (const float*)d_in[2];
    const float* zero  = (const float*)d_in[3];
    const float* lA    = (const float*)d_in[4];
    const float* lB    = (const float*)d_in[5];
    const float* bias  = (const float*)d_in[6];
    float* out = (float*)d_out;

    cudaFuncSetAttribute(mega_kernel,
                         cudaFuncAttributeMaxDynamicSharedMemorySize, GEMM_SMEM);

    // zero readiness flags (capture-safe async memset on device symbol)
    void* flags_ptr = nullptr;
    cudaGetSymbolAddress(&flags_ptr, g_flags);
    cudaMemsetAsync(flags_ptr, 0, sizeof(int) * 96, 0);

    // one launch: weff blocks -> conv blocks -> gemm blocks (spin on flags)
    mega_kernel<<<TOTAL_BLOCKS, 256, GEMM_SMEM>>>(
        (const float4*)x, wq, scale, zero, lA, lB, bias, out);
}

// round 17
// speedup vs baseline: 1.0075x; 1.0075x over previous
#include <cuda_runtime.h>
#include <cuda_fp16.h>
#include <cstdint>

// Problem dims (fixed by reference setup_inputs)
#define MM   8192      // B*S
#define NN   4096      // D_OUT
#define KK   4096      // D_IN
#define RR   16
#define LORA_SCALING 2.0f

// ---------------------------------------------------------------------------
// Device scratch (static __device__ arrays — no runtime allocation)
// ---------------------------------------------------------------------------
__device__ __half g_xh[(size_t)MM * KK];   // 64 MB: x rounded to fp16
__device__ __half g_wh[(size_t)NN * KK];   // 32 MB: fused dequant+LoRA weight, fp16
// readiness flags: [0,32) weff n-groups (128 out-rows), [32,96) conv m-groups
__device__ int g_flags[96];

// ---------------------------------------------------------------------------
// Helpers (base PTX only — sm_103 target has no 'a'-feature instructions)
// ---------------------------------------------------------------------------
__device__ __forceinline__ uint32_t smem_u32(const void* p) {
    uint32_t a;
    asm("{ .reg .u64 t; cvta.to.shared.u64 t, %1; cvt.u32.u64 %0, t; }"
        : "=r"(a) : "l"(p));
    return a;
}

#define CP_ASYNC16(dst_u32, src_ptr) \
    asm volatile("cp.async.cg.shared.global [%0], [%1], 16;\n" :: "r"(dst_u32), "l"(src_ptr))
#define CP_COMMIT()   asm volatile("cp.async.commit_group;\n" ::)
#define CP_WAIT(n)    asm volatile("cp.async.wait_group %0;\n" :: "n"(n))

#define LDMATRIX_X4(r0, r1, r2, r3, addr)                                     \
    asm volatile("ldmatrix.sync.aligned.m8n8.x4.shared.b16 {%0,%1,%2,%3}, [%4];" \
        : "=r"(r0), "=r"(r1), "=r"(r2), "=r"(r3) : "r"(addr))

#define MMA16816(d, a, b)                                                      \
    asm volatile("mma.sync.aligned.m16n8k16.row.col.f32.f16.f16.f32 "          \
        "{%0,%1,%2,%3}, {%4,%5,%6,%7}, {%8,%9}, {%0,%1,%2,%3};\n"              \
        : "+f"((d)[0]), "+f"((d)[1]), "+f"((d)[2]), "+f"((d)[3])               \
        : "r"((a)[0]), "r"((a)[1]), "r"((a)[2]), "r"((a)[3]),                  \
          "r"((b)[0]), "r"((b)[1]))

// ---------------------------------------------------------------------------
// Geometry
// ---------------------------------------------------------------------------
constexpr int WEFF_BI = 256;                   // weff tile: 64 out-rows x 256 cols
constexpr int BM = 128, BN = 128, BK = 64;     // GEMM CTA tile (R12-proven)
constexpr int NSTAGES = 3;
constexpr int A_ST = BM * 128;                 // 16 KB per stage
constexpr int STG = 2 * A_ST;                  // 32 KB per stage (A + B)
constexpr int GEMM_SMEM = NSTAGES * STG + 128;
constexpr int KT = KK / BK;                    // 64
// totals: 1024 weff + 2048 conv + 2048 gemm
constexpr int TOTAL_BLOCKS = 1024 + 2048 + 2048;   // 5120

// Dependency-interleaved schedule: 64 segments.
//   segment j: [32 conv blocks (m-group j)] [32 weff blocks (n-group j), j<32]
//              [GEMM tiles (by,bx) with max(by,bx)==j]
// Producers of any tile are in segments <= j  =>  lower bid  =>  deadlock-free.

__global__ void __launch_bounds__(256, 2)
mega_kernel(const float4* __restrict__ x,
            const int* __restrict__ wq,
            const float* __restrict__ scale,
            const float* __restrict__ zero,
            const float* __restrict__ lA,
            const float* __restrict__ lB,
            const float* __restrict__ bias,
            float* __restrict__ C) {
    extern __shared__ char dsm[];
    const int tid = threadIdx.x;

    // ---- decode bid -> (segment j, offset) ----
    unsigned off = blockIdx.x;
    int j = 0;
    #pragma unroll 1
    for (;;) {
        unsigned seg = (j < 32) ? (unsigned)(64 + 2 * j + 1) : 64u;
        if (off < seg) break;
        off -= seg; ++j;
    }

    if (off < 32) {
        // ================= conv block: rows [j*128 + off*4, +4) of x =================
        size_t base8 = ((size_t)j * 128 + (size_t)off * 4) * 512 + tid; // 8-float units
        #pragma unroll
        for (int it = 0; it < 8; it++) {
            size_t i = base8 + (size_t)it * 256;
            float4 a = x[2 * i], b = x[2 * i + 1];
            __half2 h0 = __floats2half2_rn(a.x, a.y);
            __half2 h1 = __floats2half2_rn(a.z, a.w);
            __half2 h2 = __floats2half2_rn(b.x, b.y);
            __half2 h3 = __floats2half2_rn(b.z, b.w);
            uint4 o;
            o.x = *reinterpret_cast<unsigned*>(&h0);
            o.y = *reinterpret_cast<unsigned*>(&h1);
            o.z = *reinterpret_cast<unsigned*>(&h2);
            o.w = *reinterpret_cast<unsigned*>(&h3);
            ((uint4*)g_xh)[i] = o;
        }
        __threadfence();
        __syncthreads();
        if (tid == 0) atomicAdd(&g_flags[32 + j], 1);
        return;
    }

    if (j < 32 && off < 64) {
        // ================= weff block: out rows j*128 + (w>>4)*64, cols (w&15)*256 ====
        const int w  = (int)off - 32;
        const int o0 = j * 128 + (w >> 4) * 64;
        const int i0 = (w & 15) * WEFF_BI;
        constexpr int BO = 64;

        float (*sA)[WEFF_BI] = (float (*)[WEFF_BI])dsm;                   // 16 KB
        float (*sB)[RR]      = (float (*)[RR])(dsm + RR * WEFF_BI * 4);   // 4 KB
        float* sS = (float*)(dsm + RR * WEFF_BI * 4 + BO * RR * 4);
        float* sZ = sS + BO;

        for (int idx = tid; idx < RR * WEFF_BI; idx += 256) {
            int r = idx / WEFF_BI, i = idx % WEFF_BI;
            sA[r][i] = lA[(size_t)r * KK + i0 + i];
        }
        for (int idx = tid; idx < BO * RR; idx += 256) {
            int o = idx / RR, r = idx % RR;
            sB[o][r] = lB[(size_t)(o0 + o) * RR + r];
        }
        if (tid < BO) { sS[tid] = scale[o0 + tid]; sZ[tid] = zero[o0 + tid]; }
        __syncthreads();

        constexpr int CH = WEFF_BI / 4;                  // 64 int4 chunks per row
        for (int idx = tid; idx < BO * CH; idx += 256) {
            const int o  = idx / CH;
            const int i4 = (idx % CH) * 4;
            const int4 wv = *reinterpret_cast<const int4*>(
                wq + (size_t)(o0 + o) * KK + i0 + i4);
            const float z = sZ[o], s = sS[o];
            float r0 = ((float)wv.x - z) * s;
            float r1 = ((float)wv.y - z) * s;
            float r2 = ((float)wv.z - z) * s;
            float r3 = ((float)wv.w - z) * s;
            float a0 = 0.f, a1 = 0.f, a2 = 0.f, a3 = 0.f;
            #pragma unroll
            for (int r = 0; r < RR; r++) {
                const float br = sB[o][r];
                const float4 av = *reinterpret_cast<const float4*>(&sA[r][i4]);
                a0 += br * av.x; a1 += br * av.y;
                a2 += br * av.z; a3 += br * av.w;
            }
            __half2 h01 = __floats2half2_rn(r0 + LORA_SCALING * a0,
                                            r1 + LORA_SCALING * a1);
            __half2 h23 = __floats2half2_rn(r2 + LORA_SCALING * a2,
                                            r3 + LORA_SCALING * a3);
            uint2 st;
            st.x = *reinterpret_cast<unsigned*>(&h01);
            st.y = *reinterpret_cast<unsigned*>(&h23);
            *reinterpret_cast<uint2*>(g_wh + (size_t)(o0 + o) * KK + i0 + i4) = st;
        }
        __threadfence();
        __syncthreads();
        if (tid == 0) atomicAdd(&g_flags[j], 1);
        return;
    }

    // ================= GEMM tile =================
    int by, bx;
    {
        const int t = (int)off - (j < 32 ? 64 : 32);
        if (j < 32) { if (t <= j) { by = j; bx = t; } else { by = t - j - 1; bx = j; } }
        else        { by = j; bx = t; }
    }
    const int m0 = by * BM;
    const int n0 = bx * BN;

    // wait for producers (weff n-group bx, conv m-group by)
    if (tid == 0) {
        volatile int* fw = &g_flags[bx];
        volatile int* fx = &g_flags[32 + by];
        while (*fw < 32) { __nanosleep(100); }
        while (*fx < 32) { __nanosleep(100); }
        __threadfence();
    }
    __syncthreads();

    const uint32_t tile = (smem_u32(dsm) + 127u) & ~127u;   // 128B-align
    const int warp = tid >> 5;
    const int lane = tid & 31;

    // ---- cp.async mapping: 2048 16B chunks / 256 threads = 8 each (4 A, 4 B)
    const __half* gA = g_xh + (size_t)m0 * KK;
    const __half* gB = g_wh + (size_t)n0 * KK;
    uint32_t soff[8];
    uint32_t doff[8];
    #pragma unroll
    for (int jj = 0; jj < 8; jj++) {
        int c = tid + (jj & 3) * 256;
        int row = c >> 3, c16 = c & 7;
        soff[jj] = (uint32_t)(row * KK + c16 * 8);
        doff[jj] = (uint32_t)((jj < 4 ? 0 : A_ST) + row * 128 + ((c16 ^ (row & 7)) << 4));
    }

    #define ISSUE_STAGE(kt_, s_) do {                                          \
        uint32_t base_ = tile + (s_) * STG;                                    \
        _Pragma("unroll")                                                      \
        for (int q = 0; q < 4; q++)                                            \
            CP_ASYNC16(base_ + doff[q], gA + soff[q] + (kt_) * BK);            \
        _Pragma("unroll")                                                      \
        for (int q = 4; q < 8; q++)                                            \
            CP_ASYNC16(base_ + doff[q], gB + soff[q] + (kt_) * BK);            \
        CP_COMMIT();                                                           \
    } while (0)

    const int wm = (warp & 3) * 32;
    const int wn = (warp >> 2) * 64;
    const int gid = lane >> 2;
    const int tig = lane & 3;
    const int l7  = lane & 7;

    uint32_t a_row[2];
    #pragma unroll
    for (int mi = 0; mi < 2; mi++)
        a_row[mi] = (uint32_t)((wm + mi * 16 + (lane & 15)) * 128);
    const uint32_t a_cx = (uint32_t)(lane >> 4);
    uint32_t b_row[4];
    #pragma unroll
    for (int ng = 0; ng < 4; ng++)
        b_row[ng] = (uint32_t)((wn + ng * 16 + l7 + ((lane >> 4) << 3)) * 128);
    const uint32_t b_cx = (uint32_t)((lane >> 3) & 1);

    float acc[2][8][4];
    #pragma unroll
    for (int a = 0; a < 2; a++)
        #pragma unroll
        for (int b = 0; b < 8; b++)
            #pragma unroll
            for (int c = 0; c < 4; c++) acc[a][b][c] = 0.f;

    ISSUE_STAGE(0, 0);
    ISSUE_STAGE(1, 1);

    int s = 0;
    for (int kt = 0; kt < KT; kt++) {
        CP_WAIT(1);
        __syncthreads();
        if (kt + 2 < KT) {
            int sn = s + 2; if (sn >= NSTAGES) sn -= NSTAGES;
            ISSUE_STAGE(kt + 2, sn);
        }

        const uint32_t sA = tile + s * STG;
        const uint32_t sB = sA + A_ST;

        #pragma unroll
        for (int ks = 0; ks < 4; ks++) {
            const uint32_t kc = (uint32_t)(ks * 2);
            uint32_t af[2][4], bf[8][2];
            #pragma unroll
            for (int mi = 0; mi < 2; mi++) {
                uint32_t addr = sA + a_row[mi] + (((kc + a_cx) ^ l7) << 4);
                LDMATRIX_X4(af[mi][0], af[mi][1], af[mi][2], af[mi][3], addr);
            }
            #pragma unroll
            for (int ng = 0; ng < 4; ng++) {
                uint32_t addr = sB + b_row[ng] + (((kc + b_cx) ^ l7) << 4);
                LDMATRIX_X4(bf[2 * ng][0], bf[2 * ng][1],
                            bf[2 * ng + 1][0], bf[2 * ng + 1][1], addr);
            }
            #pragma unroll
            for (int mi = 0; mi < 2; mi++)
                #pragma unroll
                for (int ni = 0; ni < 8; ni++)
                    MMA16816(acc[mi][ni], af[mi], bf[ni]);
        }
        if (++s == NSTAGES) s = 0;
    }

    #pragma unroll
    for (int mi = 0; mi < 2; mi++) {
        const int row0 = m0 + wm + mi * 16 + gid;
        #pragma unroll
        for (int ni = 0; ni < 8; ni++) {
            const int col = n0 + wn + ni * 8 + tig * 2;
            const float b0 = __ldg(bias + col);
            const float b1 = __ldg(bias + col + 1);
            float2 v0 = make_float2(acc[mi][ni][0] + b0, acc[mi][ni][1] + b1);
            float2 v1 = make_float2(acc[mi][ni][2] + b0, acc[mi][ni][3] + b1);
            *(float2*)(C + (size_t)row0 * NN + col)       = v0;
            *(float2*)(C + (size_t)(row0 + 8) * NN + col) = v1;
        }
    }
    #undef ISSUE_STAGE
}

// ---------------------------------------------------------------------------
// Launch
// ---------------------------------------------------------------------------
extern "C" void kernel_launch(void* const* d_in, const int* in_sizes, int n_in,
                              void* d_out, int out_size) {
    const float* x     = (const float*)d_in[0];
    const int*   wq    = (const int*)  d_in[1];
    const float* scale = (const float*)d_in[2];
    const float* zero  = (const float*)d_in[3];
    const float* lA    = (const float*)d_in[4];
    const float* lB    = (const float*)d_in[5];
    const float* bias  = (const float*)d_in[6];
    float* out = (float*)d_out;

    cudaFuncSetAttribute(mega_kernel,
                         cudaFuncAttributeMaxDynamicSharedMemorySize, GEMM_SMEM);

    // zero readiness flags (capture-safe async memset on device symbol)
    void* flags_ptr = nullptr;
    cudaGetSymbolAddress(&flags_ptr, g_flags);
    cudaMemsetAsync(flags_ptr, 0, sizeof(int) * 96, 0);

    // one launch, dependency-interleaved schedule (prep overlaps GEMM)
    mega_kernel<<<TOTAL_BLOCKS, 256, GEMM_SMEM>>>(
        (const float4*)x, wq, scale, zero, lA, lB, bias, out);
}